// round 16
// baseline (speedup 1.0000x reference)
#include <cuda_runtime.h>
#include <cuda_fp16.h>
#include <cstdint>

// MinHashSketch: sketch[s][h] = min over nodes m in segment s of dot(x[m], H[h]),
// empty segments -> 0.  x:[500000,256] f32, batch:[500000] i64/i32 (detected),
// H:[128,256] f32, out:[512,128] f32.
//
// Warp-specialized persistent fp16 m16n8k16 GEMM, 512 threads, with
// SPLIT producer/consumer synchronization (named barriers) and a 4-deep ring:
//   warps 8-15 (producers): LDG x -> cvt fp16 -> STS fragment-layout A chunks
//       (BK=64) into a 4-deep ring; bar.arrive(FULL), bar.sync(EMPTY) only.
//       Free-run up to one full tile ahead -> epilogue fully covered.
//   warps 0-7  (consumers): bar.sync(FULL), LDS + mma (mt2 x nt8 each,
//       2 mma warps per SMSP), bar.arrive(EMPTY), then fused segment-min
//       epilogue while producers stream the next tile.
// B (=H) staged once per CTA. Order-preserving uint encoding + atomicMin.

#define NODES 500000
#define FDIM 256
#define NH   128
#define NSEG 512

#define BM   128
#define BK   64
#define CPT  (FDIM / BK)          // 4 chunks per tile
#define NKS  (FDIM / 16)          // 16 global k-steps
#define THREADS 512
#define NTILES ((NODES + BM - 1) / BM)   // 3907
#define RING 4

// B fragment smem (b32 words, 2 fp16/word): 8 n-pairs * 16 ks * 132
#define B_KS_STRIDE   132
#define B_PAIR_STRIDE (NKS * B_KS_STRIDE)    // 2112
#define SM_B_WORDS    (8 * B_PAIR_STRIDE)    // 16896
// A fragment smem: per chunk 8 mt * 4 ksl * 132; RING buffers
#define A_KS_STRIDE   132
#define A_MT_STRIDE   (4 * A_KS_STRIDE)      // 528
#define A_BUF_WORDS   (8 * A_MT_STRIDE)      // 4224
#define SM_A_OFF      SM_B_WORDS
#define SMEM_BYTES    ((SM_B_WORDS + RING * A_BUF_WORDS) * 4)   // ~135 KB

// named barriers: FULL[s] = 1+s, EMPTY[s] = 1+RING+s, consumer-only = 9+RING... use 15
#define BAR_FULL(s)  (1 + (s))
#define BAR_EMPTY(s) (1 + RING + (s))
#define BAR_CONS     15

__device__ __forceinline__ void bar_sync_n(int id, int cnt) {
    asm volatile("bar.sync %0, %1;" :: "r"(id), "r"(cnt) : "memory");
}
__device__ __forceinline__ void bar_arrive_n(int id, int cnt) {
    asm volatile("bar.arrive %0, %1;" :: "r"(id), "r"(cnt) : "memory");
}

__device__ __forceinline__ unsigned fenc(float f) {
    unsigned u = __float_as_uint(f);
    return (u & 0x80000000u) ? ~u : (u | 0x80000000u);
}

__device__ __forceinline__ unsigned packh2(float lo, float hi) {
    __half2 h = __floats2half2_rn(lo, hi);
    return *reinterpret_cast<unsigned*>(&h);
}

__device__ __forceinline__ void mma16(float* c, const unsigned* a, const unsigned* b) {
    asm volatile(
        "mma.sync.aligned.m16n8k16.row.col.f32.f16.f16.f32 "
        "{%0,%1,%2,%3}, {%4,%5,%6,%7}, {%8,%9}, {%0,%1,%2,%3};"
        : "+f"(c[0]), "+f"(c[1]), "+f"(c[2]), "+f"(c[3])
        : "r"(a[0]), "r"(a[1]), "r"(a[2]), "r"(a[3]), "r"(b[0]), "r"(b[1]));
}

__global__ void init_kernel(unsigned* outu) {
    int i = blockIdx.x * blockDim.x + threadIdx.x;
    if (i < NSEG * NH) outu[i] = 0xFFFFFFFFu;
}

__global__ void decode_kernel(float* out) {
    int i = blockIdx.x * blockDim.x + threadIdx.x;
    if (i < NSEG * NH) {
        unsigned u = __float_as_uint(out[i]);
        float f;
        if (u == 0xFFFFFFFFu) f = 0.0f;   // empty segment -> 0
        else f = (u & 0x80000000u) ? __uint_as_float(u ^ 0x80000000u) : __uint_as_float(~u);
        out[i] = f;
    }
}

// ---- producer helpers: chunk = [128 rows x 64 phys cols] of x, 256 threads ----
__device__ __forceinline__ void fetchA(float4* v, const float* __restrict__ x,
                                       int m0, int bk, int ptid) {
#pragma unroll
    for (int it = 0; it < 8; it++) {
        int idx = ptid + it * 256;
        int row = idx >> 4, col4 = idx & 15;
        int m = m0 + row;
        v[it] = (m < NODES)
            ? *(const float4*)(x + (size_t)m * FDIM + bk * BK + col4 * 4)
            : make_float4(0.f, 0.f, 0.f, 0.f);
    }
}

__device__ __forceinline__ void stsA(const float4* v, unsigned* Asm, int buf, int ptid) {
    unsigned* base = Asm + buf * A_BUF_WORDS;
#pragma unroll
    for (int it = 0; it < 8; it++) {
        int idx = ptid + it * 256;
        int row = idx >> 4, col4 = idx & 15;
        int mt = row >> 4, rr = row & 15;
        int g = rr & 7, hi = rr >> 3;
        int ksl = col4 >> 2, t4 = col4 & 3;
        int woff = mt * A_MT_STRIDE + ksl * A_KS_STRIDE + (g * 4 + t4) * 4 + hi * 2;
        uint2 w;
        w.x = packh2(v[it].x, v[it].y);   // klo pair
        w.y = packh2(v[it].z, v[it].w);   // khi pair
        *(uint2*)(base + woff) = w;       // per lane-uint4 word order: {a0,a2,a1,a3}
    }
}

__global__ void __launch_bounds__(THREADS, 1)
mm_kernel(const float* __restrict__ x, const void* __restrict__ batch_raw,
          const float* __restrict__ H, unsigned* __restrict__ outu) {
    extern __shared__ unsigned smw[];
    unsigned* Bfu = smw;
    unsigned* Asm = smw + SM_A_OFF;

    const int tid = threadIdx.x;
    const int wid = tid >> 5, lane = tid & 31;
    const int is64 = (((const int*)batch_raw)[NODES - 1] == 0);

    if (wid >= 8) {
        // ====================== PRODUCERS (warps 8-15) ======================
        const int ptid = tid - 256;
        int tp = blockIdx.x, bkp = 0;
        int c = 0;                        // global chunk counter
        float4 v[2][8];
        int cur = 0;
        fetchA(v[cur], x, tp * BM, 0, ptid);
        for (;;) {
            // issue next chunk's LDGs before any waiting (overlap DRAM latency)
            int tn = tp, bn = bkp + 1;
            if (bn == CPT) { bn = 0; tn += gridDim.x; }
            bool have = (tn < NTILES);
            if (have) fetchA(v[cur ^ 1], x, tn * BM, bn, ptid);

            int buf = c & (RING - 1);
            if (c >= RING) bar_sync_n(BAR_EMPTY(buf), 512);
            stsA(v[cur], Asm, buf, ptid);
            asm volatile("membar.cta;" ::: "memory");
            bar_arrive_n(BAR_FULL(buf), 512);

            if (!have) break;
            tp = tn; bkp = bn; c++; cur ^= 1;
        }
    } else {
        // ====================== CONSUMERS (warps 0-7) =======================
        const int wm = wid >> 1, wn = wid & 1;   // 4 (M) x 2 (N)
        const int tt = lane & 3;

        // Stage B = H once (k-permuted: logical {2t,2t+1,2t+8,2t+9} at phys 4t..4t+3)
        for (int i = tid; i < (NH * FDIM) / 4; i += 256) {
            int n = i >> 6;
            int col4 = i & 63;
            int ks = col4 >> 2, t4 = col4 & 3;
            float4 hv = ((const float4*)H)[i];
            int pp = n >> 4, half = (n >> 3) & 1;
            int lane0 = ((n & 7) << 2) | t4;
            unsigned* b = Bfu + pp * B_PAIR_STRIDE + ks * B_KS_STRIDE + lane0 * 4 + half * 2;
            b[0] = packh2(hv.x, hv.y);
            b[1] = packh2(hv.z, hv.w);
        }
        bar_sync_n(BAR_CONS, 256);        // consumers only; producers independent

        const unsigned* Bw = Bfu + wn * 4 * B_PAIR_STRIDE + lane * 4;
        int cc = 0;                        // consumer chunk counter

        for (int t = blockIdx.x; t < NTILES; t += gridDim.x) {
            const int m0 = t * BM;

            // prefetch segment ids early (hidden under the chunk waits)
            bool full = (m0 + BM) <= NODES;
            int sF = is64 ? (int)((const long long*)batch_raw)[m0]
                          : ((const int*)batch_raw)[m0];
            int sL = -2;
            if (full)
                sL = is64 ? (int)((const long long*)batch_raw)[m0 + BM - 1]
                          : ((const int*)batch_raw)[m0 + BM - 1];

            float acc[2][8][4];
#pragma unroll
            for (int i = 0; i < 2; i++)
#pragma unroll
                for (int j = 0; j < 8; j++)
#pragma unroll
                    for (int c2 = 0; c2 < 4; c2++) acc[i][j][c2] = 0.f;

            for (int bk = 0; bk < CPT; bk++, cc++) {
                int buf = cc & (RING - 1);
                bar_sync_n(BAR_FULL(buf), 512);
                const unsigned* Ab = Asm + buf * A_BUF_WORDS + wm * 2 * A_MT_STRIDE + lane * 4;
#pragma unroll
                for (int ksl = 0; ksl < 4; ksl++) {
                    int ksg = bk * 4 + ksl;
                    uint4 av[2];
#pragma unroll
                    for (int i = 0; i < 2; i++)
                        av[i] = *(const uint4*)(Ab + i * A_MT_STRIDE + ksl * A_KS_STRIDE);
                    unsigned b[8][2];
#pragma unroll
                    for (int q = 0; q < 4; q++) {
                        uint4 bv = *(const uint4*)(Bw + q * B_PAIR_STRIDE + ksg * B_KS_STRIDE);
                        b[2 * q][0] = bv.x;     b[2 * q][1] = bv.y;
                        b[2 * q + 1][0] = bv.z; b[2 * q + 1][1] = bv.w;
                    }
#pragma unroll
                    for (int i = 0; i < 2; i++) {
                        unsigned a[4] = {av[i].x, av[i].z, av[i].y, av[i].w};
#pragma unroll
                        for (int j = 0; j < 8; j++)
                            mma16(acc[i][j], a, b[j]);
                    }
                }
                // mma operands consumed (data-dependent) -> safe to release buffer
                bar_arrive_n(BAR_EMPTY(buf), 512);
            }

            // ---- fused segment-min epilogue (producers stream next tile) ----
            if (full && sF == sL) {
#pragma unroll
                for (int j = 0; j < 8; j++) {
                    float v0 = fminf(fminf(acc[0][j][0], acc[0][j][2]),
                                     fminf(acc[1][j][0], acc[1][j][2]));
                    float v1 = fminf(fminf(acc[0][j][1], acc[0][j][3]),
                                     fminf(acc[1][j][1], acc[1][j][3]));
#pragma unroll
                    for (int off = 4; off < 32; off <<= 1) {
                        v0 = fminf(v0, __shfl_xor_sync(0xffffffffu, v0, off));
                        v1 = fminf(v1, __shfl_xor_sync(0xffffffffu, v1, off));
                    }
                    if (lane < 4) {
                        int col = wn * 64 + j * 8 + lane * 2;
                        atomicMin(&outu[sF * NH + col],     fenc(v0));
                        atomicMin(&outu[sF * NH + col + 1], fenc(v1));
                    }
                }
            } else {
                const int g = lane >> 2;
#pragma unroll
                for (int i = 0; i < 2; i++) {
#pragma unroll
                    for (int h = 0; h < 2; h++) {
                        int m = m0 + wm * 32 + i * 16 + g + h * 8;
                        if (m < NODES) {
                            int s = is64 ? (int)((const long long*)batch_raw)[m]
                                         : ((const int*)batch_raw)[m];
                            unsigned* dst = outu + s * NH + wn * 64 + tt * 2;
#pragma unroll
                            for (int j = 0; j < 8; j++) {
                                atomicMin(dst + j * 8,     fenc(acc[i][j][h * 2 + 0]));
                                atomicMin(dst + j * 8 + 1, fenc(acc[i][j][h * 2 + 1]));
                            }
                        }
                    }
                }
            }
        }
    }
}

extern "C" void kernel_launch(void* const* d_in, const int* in_sizes, int n_in,
                              void* d_out, int out_size) {
    const float* x = nullptr;
    const void* batch = nullptr;
    const float* H = nullptr;
    for (int i = 0; i < n_in; i++) {
        int s = in_sizes[i];
        if (s == NODES * FDIM) x = (const float*)d_in[i];
        else if (s == NODES) batch = d_in[i];
        else if (s == NH * FDIM) H = (const float*)d_in[i];
    }
    unsigned* outu = (unsigned*)d_out;

    int nsm = 148;
    cudaDeviceGetAttribute(&nsm, cudaDevAttrMultiProcessorCount, 0);
    cudaFuncSetAttribute(mm_kernel, cudaFuncAttributeMaxDynamicSharedMemorySize, SMEM_BYTES);

    init_kernel<<<(NSEG * NH + 255) / 256, 256>>>(outu);
    mm_kernel<<<nsm, THREADS, SMEM_BYTES>>>(x, batch, H, outu);
    decode_kernel<<<(NSEG * NH + 255) / 256, 256>>>((float*)d_out);
}

// round 17
// speedup vs baseline: 1.3311x; 1.3311x over previous
#include <cuda_runtime.h>
#include <cuda_fp16.h>
#include <cstdint>

// MinHashSketch: sketch[s][h] = min over nodes m in segment s of dot(x[m], H[h]),
// empty segments -> 0.  x:[500000,256] f32, batch:[500000] i64/i32 (detected),
// H:[128,256] f32, out:[512,128] f32.
//
// Single persistent kernel (init + GEMM + decode fused via monotonic grid
// barriers; grid == #SMs so all CTAs are resident and spinning is safe).
// Warp-specialized fp16 m16n8k16 GEMM, 512 threads:
//   warps 8-15 (producers): LDG x -> cvt fp16 -> STS fragment-layout A chunks
//                           (BK=64) into a 2-deep ring, distance-1 prefetch.
//   warps 0-7  (consumers): LDS + mma (mt2 x nt8 each; 2 mma warps per SMSP),
//                           fused segment-min epilogue inside last interval.
// B (=H) staged once per CTA. Order-preserving uint encoding + atomicMin.

#define NODES 500000
#define FDIM 256
#define NH   128
#define NSEG 512

#define BM   128
#define BK   64
#define CPT  (FDIM / BK)          // 4 chunks per tile
#define NKS  (FDIM / 16)          // 16 global k-steps
#define THREADS 512
#define NTILES ((NODES + BM - 1) / BM)   // 3907

// B fragment smem (b32 words, 2 fp16/word): 8 n-pairs * 16 ks * 132
#define B_KS_STRIDE   132
#define B_PAIR_STRIDE (NKS * B_KS_STRIDE)    // 2112
#define SM_B_WORDS    (8 * B_PAIR_STRIDE)    // 16896
// A fragment smem: per chunk 8 mt * 4 ksl * 132; 2 buffers
#define A_KS_STRIDE   132
#define A_MT_STRIDE   (4 * A_KS_STRIDE)      // 528
#define A_BUF_WORDS   (8 * A_MT_STRIDE)      // 4224
#define SM_A_OFF      SM_B_WORDS
#define SMEM_BYTES    ((SM_B_WORDS + 2 * A_BUF_WORDS) * 4)   // ~101 KB

__device__ unsigned long long g_cnt;   // monotonic grid-barrier counter

__device__ __forceinline__ void grid_barrier() {
    __threadfence();
    __syncthreads();
    if (threadIdx.x == 0) {
        unsigned long long t = atomicAdd(&g_cnt, 1ULL);
        unsigned long long target = (t / gridDim.x + 1ULL) * gridDim.x;
        unsigned long long v;
        do {
            asm volatile("ld.volatile.global.u64 %0, [%1];" : "=l"(v) : "l"(&g_cnt));
        } while (v < target);
    }
    __syncthreads();
    __threadfence();
}

__device__ __forceinline__ unsigned fenc(float f) {
    unsigned u = __float_as_uint(f);
    return (u & 0x80000000u) ? ~u : (u | 0x80000000u);
}

__device__ __forceinline__ unsigned packh2(float lo, float hi) {
    __half2 h = __floats2half2_rn(lo, hi);
    return *reinterpret_cast<unsigned*>(&h);
}

__device__ __forceinline__ void mma16(float* c, const unsigned* a, const unsigned* b) {
    asm volatile(
        "mma.sync.aligned.m16n8k16.row.col.f32.f16.f16.f32 "
        "{%0,%1,%2,%3}, {%4,%5,%6,%7}, {%8,%9}, {%0,%1,%2,%3};"
        : "+f"(c[0]), "+f"(c[1]), "+f"(c[2]), "+f"(c[3])
        : "r"(a[0]), "r"(a[1]), "r"(a[2]), "r"(a[3]), "r"(b[0]), "r"(b[1]));
}

// ---- producer helpers: chunk = [128 rows x 64 phys cols] of x, 256 threads ----
__device__ __forceinline__ void fetchA(float4* v, const float* __restrict__ x,
                                       int m0, int bk, int ptid) {
#pragma unroll
    for (int it = 0; it < 8; it++) {
        int idx = ptid + it * 256;
        int row = idx >> 4, col4 = idx & 15;
        int m = m0 + row;
        v[it] = (m < NODES)
            ? *(const float4*)(x + (size_t)m * FDIM + bk * BK + col4 * 4)
            : make_float4(0.f, 0.f, 0.f, 0.f);
    }
}

__device__ __forceinline__ void stsA(const float4* v, unsigned* Asm, int buf, int ptid) {
    unsigned* base = Asm + buf * A_BUF_WORDS;
#pragma unroll
    for (int it = 0; it < 8; it++) {
        int idx = ptid + it * 256;
        int row = idx >> 4, col4 = idx & 15;
        int mt = row >> 4, rr = row & 15;
        int g = rr & 7, hi = rr >> 3;
        int ksl = col4 >> 2, t4 = col4 & 3;
        int woff = mt * A_MT_STRIDE + ksl * A_KS_STRIDE + (g * 4 + t4) * 4 + hi * 2;
        uint2 w;
        w.x = packh2(v[it].x, v[it].y);   // klo pair
        w.y = packh2(v[it].z, v[it].w);   // khi pair
        *(uint2*)(base + woff) = w;       // per lane-uint4 word order: {a0,a2,a1,a3}
    }
}

__global__ void __launch_bounds__(THREADS, 1)
mm_kernel(const float* __restrict__ x, const void* __restrict__ batch_raw,
          const float* __restrict__ H, unsigned* __restrict__ outu) {
    extern __shared__ unsigned smw[];
    unsigned* Bfu = smw;
    unsigned* Asm = smw + SM_A_OFF;

    const int tid = threadIdx.x;
    const int wid = tid >> 5, lane = tid & 31;
    const int is64 = (((const int*)batch_raw)[NODES - 1] == 0);

    // ---- phase 0: init output to encoded +inf (0xFFFFFFFF) ----
    for (int i = blockIdx.x * THREADS + tid; i < NSEG * NH; i += gridDim.x * THREADS)
        outu[i] = 0xFFFFFFFFu;
    grid_barrier();

    if (wid >= 8) {
        // ====================== PRODUCERS (warps 8-15) ======================
        const int ptid = tid - 256;
        int tp = blockIdx.x, bkp = 0;
        float4 v[8];
        fetchA(v, x, tp * BM, 0, ptid);
        stsA(v, Asm, 0, ptid);
        bkp = 1;
        fetchA(v, x, tp * BM, bkp, ptid);     // chunk 1 (CPT>=2 always)
        __syncthreads();                       // #0: buf0 full
        int buf = 1;
        for (;;) {
            stsA(v, Asm, buf, ptid);
            if (++bkp == CPT) { bkp = 0; tp += gridDim.x; }
            bool have = (tp < NTILES);
            if (have) fetchA(v, x, tp * BM, bkp, ptid);
            __syncthreads();
            buf ^= 1;
            if (!have) break;
        }
    } else {
        // ====================== CONSUMERS (warps 0-7) =======================
        const int wm = wid >> 1, wn = wid & 1;   // 4 (M) x 2 (N)
        const int tt = lane & 3;

        // Stage B = H once (k-permuted: logical {2t,2t+1,2t+8,2t+9} at phys 4t..4t+3)
        for (int i = tid; i < (NH * FDIM) / 4; i += 256) {
            int n = i >> 6;
            int col4 = i & 63;
            int ks = col4 >> 2, t4 = col4 & 3;
            float4 hv = ((const float4*)H)[i];
            int pp = n >> 4, half = (n >> 3) & 1;
            int lane0 = ((n & 7) << 2) | t4;
            unsigned* b = Bfu + pp * B_PAIR_STRIDE + ks * B_KS_STRIDE + lane0 * 4 + half * 2;
            b[0] = packh2(hv.x, hv.y);
            b[1] = packh2(hv.z, hv.w);
        }
        __syncthreads();                       // #0

        const unsigned* Bw = Bfu + wn * 4 * B_PAIR_STRIDE + lane * 4;
        int buf = 0;

        for (int t = blockIdx.x; t < NTILES; t += gridDim.x) {
            const int m0 = t * BM;
            const bool lastTile = (t + gridDim.x >= NTILES);

            // prefetch segment ids early (hidden under chunk processing)
            bool full = (m0 + BM) <= NODES;
            int sF = is64 ? (int)((const long long*)batch_raw)[m0]
                          : ((const int*)batch_raw)[m0];
            int sL = -2;
            if (full)
                sL = is64 ? (int)((const long long*)batch_raw)[m0 + BM - 1]
                          : ((const int*)batch_raw)[m0 + BM - 1];

            float acc[2][8][4];
#pragma unroll
            for (int i = 0; i < 2; i++)
#pragma unroll
                for (int j = 0; j < 8; j++)
#pragma unroll
                    for (int c = 0; c < 4; c++) acc[i][j][c] = 0.f;

            for (int bk = 0; bk < CPT; bk++) {
                const unsigned* Ab = Asm + buf * A_BUF_WORDS + wm * 2 * A_MT_STRIDE + lane * 4;
#pragma unroll
                for (int ksl = 0; ksl < 4; ksl++) {
                    int ksg = bk * 4 + ksl;
                    uint4 av[2];
#pragma unroll
                    for (int i = 0; i < 2; i++)
                        av[i] = *(const uint4*)(Ab + i * A_MT_STRIDE + ksl * A_KS_STRIDE);
                    unsigned b[8][2];
#pragma unroll
                    for (int q = 0; q < 4; q++) {
                        uint4 bv = *(const uint4*)(Bw + q * B_PAIR_STRIDE + ksg * B_KS_STRIDE);
                        b[2 * q][0] = bv.x;     b[2 * q][1] = bv.y;
                        b[2 * q + 1][0] = bv.z; b[2 * q + 1][1] = bv.w;
                    }
#pragma unroll
                    for (int i = 0; i < 2; i++) {
                        unsigned a[4] = {av[i].x, av[i].z, av[i].y, av[i].w};
#pragma unroll
                        for (int j = 0; j < 8; j++)
                            mma16(acc[i][j], a, b[j]);
                    }
                }
                buf ^= 1;

                if (bk == CPT - 1) {
                    // ---- fused segment-min epilogue (inside last interval) ----
                    if (full && sF == sL) {
#pragma unroll
                        for (int j = 0; j < 8; j++) {
                            float v0 = fminf(fminf(acc[0][j][0], acc[0][j][2]),
                                             fminf(acc[1][j][0], acc[1][j][2]));
                            float v1 = fminf(fminf(acc[0][j][1], acc[0][j][3]),
                                             fminf(acc[1][j][1], acc[1][j][3]));
#pragma unroll
                            for (int off = 4; off < 32; off <<= 1) {
                                v0 = fminf(v0, __shfl_xor_sync(0xffffffffu, v0, off));
                                v1 = fminf(v1, __shfl_xor_sync(0xffffffffu, v1, off));
                            }
                            if (lane < 4) {
                                int col = wn * 64 + j * 8 + lane * 2;
                                atomicMin(&outu[sF * NH + col],     fenc(v0));
                                atomicMin(&outu[sF * NH + col + 1], fenc(v1));
                            }
                        }
                    } else {
                        const int g = lane >> 2;
#pragma unroll
                        for (int i = 0; i < 2; i++) {
#pragma unroll
                            for (int h = 0; h < 2; h++) {
                                int m = m0 + wm * 32 + i * 16 + g + h * 8;
                                if (m < NODES) {
                                    int s = is64 ? (int)((const long long*)batch_raw)[m]
                                                 : ((const int*)batch_raw)[m];
                                    unsigned* dst = outu + s * NH + wn * 64 + tt * 2;
#pragma unroll
                                    for (int j = 0; j < 8; j++) {
                                        atomicMin(dst + j * 8,     fenc(acc[i][j][h * 2 + 0]));
                                        atomicMin(dst + j * 8 + 1, fenc(acc[i][j][h * 2 + 1]));
                                    }
                                }
                            }
                        }
                    }
                    if (!lastTile) __syncthreads();
                } else {
                    __syncthreads();
                }
            }
        }
    }

    // ---- phase 2: decode (after ALL CTAs' atomics) ----
    grid_barrier();
    for (int i = blockIdx.x * THREADS + tid; i < NSEG * NH; i += gridDim.x * THREADS) {
        unsigned u;
        asm volatile("ld.global.cg.u32 %0, [%1];" : "=r"(u) : "l"(outu + i));
        float f;
        if (u == 0xFFFFFFFFu) f = 0.0f;   // empty segment -> 0
        else f = (u & 0x80000000u) ? __uint_as_float(u ^ 0x80000000u) : __uint_as_float(~u);
        outu[i] = __float_as_uint(f);
    }
}

extern "C" void kernel_launch(void* const* d_in, const int* in_sizes, int n_in,
                              void* d_out, int out_size) {
    const float* x = nullptr;
    const void* batch = nullptr;
    const float* H = nullptr;
    for (int i = 0; i < n_in; i++) {
        int s = in_sizes[i];
        if (s == NODES * FDIM) x = (const float*)d_in[i];
        else if (s == NODES) batch = d_in[i];
        else if (s == NH * FDIM) H = (const float*)d_in[i];
    }
    unsigned* outu = (unsigned*)d_out;

    int nsm = 148;
    cudaDeviceGetAttribute(&nsm, cudaDevAttrMultiProcessorCount, 0);
    cudaFuncSetAttribute(mm_kernel, cudaFuncAttributeMaxDynamicSharedMemorySize, SMEM_BYTES);

    mm_kernel<<<nsm, THREADS, SMEM_BYTES>>>(x, batch, H, outu);
}